// round 9
// baseline (speedup 1.0000x reference)
#include <cuda_runtime.h>
#include <cuda_bf16.h>

#define SS   8
#define HH   544
#define WW   960
#define HID  64
#define BT   256
#define FULL 0xffffffffu

__device__ int g_ctr;

__global__ void zero_ctr_kernel() { g_ctr = 0; }

__global__ __launch_bounds__(BT)
void sky_kernel(const float* __restrict__ images,
                const float* __restrict__ extr,
                const float* __restrict__ intr,
                const float* __restrict__ W1,
                const float* __restrict__ b1,
                const float* __restrict__ W2,
                const float* __restrict__ b2,
                const float* __restrict__ pcd,
                const float* __restrict__ lsc,
                const int*   __restrict__ dsp,
                float* __restrict__ out, int N, int NW)
{
    __shared__ float  sE[SS * 12];
    __shared__ float  sK[SS * 9];
    __shared__ float4 sW14[HID];   // {W1r0[j], W1r1[j], W1r2[j], b1[j]}
    __shared__ float4 sW24[HID];   // {W2[j][0], W2[j][1], W2[j][2], 0}
    __shared__ float  sB2[3];

    const int tid  = threadIdx.x;
    const int lane = tid & 31;

    float ds;
    {
        int iv = *dsp;
        ds = (iv > 0 && iv < 1000000) ? (float)iv : __int_as_float(iv);
    }

    if (tid < SS * 12) sE[tid] = extr[(tid / 12) * 16 + (tid % 12)];
    if (tid < SS * 9) {
        int ij = tid % 9, i = ij / 3, j = ij % 3;
        float d = 1.0f;
        if (i == 0 && (j == 0 || j == 2)) d = ds;
        if (i == 1 && (j == 1 || j == 2)) d = ds;
        sK[tid] = intr[tid] / d;
    }
    if (tid < HID) {
        sW14[tid] = make_float4(W1[tid], W1[HID + tid], W1[2 * HID + tid], b1[tid]);
        sW24[tid] = make_float4(W2[tid * 6 + 0], W2[tid * 6 + 1], W2[tid * 6 + 2], 0.f);
    }
    if (tid < 3) sB2[tid] = b2[tid];
    __syncthreads();

    // ---- dynamic work stealing: one 32-point chunk per grab ----
    while (true) {
        int chunk;
        if (lane == 0) chunk = atomicAdd(&g_ctr, 1);
        chunk = __shfl_sync(FULL, chunk, 0);
        if (chunk >= NW) break;

        const int n = (chunk << 5) + lane;
        if (n >= N) continue;

        const float X = pcd[3 * n + 0];
        const float Y = pcd[3 * n + 1];
        const float Z = pcd[3 * n + 2];

        float f0 = 0.f, f1 = 0.f, f2 = 0.f, cnt = 0.f;

        #pragma unroll
        for (int s = 0; s < SS; ++s) {
            const float* E = sE + s * 12;
            const float* K = sK + s * 9;
            float c0 = E[0] * X + E[1]  * Y + E[2]  * Z + E[3];
            float c1 = E[4] * X + E[5]  * Y + E[6]  * Z + E[7];
            float c2 = E[8] * X + E[9]  * Y + E[10] * Z + E[11];
            float u = K[0] * c0 + K[1] * c1 + K[2] * c2;
            float v = K[3] * c0 + K[4] * c1 + K[5] * c2;
            float w = K[6] * c0 + K[7] * c1 + K[8] * c2;
            float zs = (fabsf(w) > 1e-6f) ? w : 1e-6f;
            float px = u / zs;
            float py = v / zs;
            bool m = (w > 0.001f) && (px >= 0.f) && (px <= (float)(WW - 1)) &&
                     (py >= 0.f) && (py <= (float)(HH - 1));
            if (m) {
                int x0 = (int)floorf(px); x0 = min(max(x0, 0), WW - 2);
                int y0 = (int)floorf(py); y0 = min(max(y0, 0), HH - 2);
                float wx = px - (float)x0;
                float wy = py - (float)y0;
                float w00 = (1.f - wx) * (1.f - wy);
                float w01 = wx * (1.f - wy);
                float w10 = (1.f - wx) * wy;
                float w11 = wx * wy;
                const float* img = images + (size_t)s * 3 * HH * WW + (size_t)y0 * WW + x0;
                {
                    const float* p = img;
                    f0 += p[0] * w00 + p[1] * w01 + p[WW] * w10 + p[WW + 1] * w11;
                }
                {
                    const float* p = img + (size_t)HH * WW;
                    f1 += p[0] * w00 + p[1] * w01 + p[WW] * w10 + p[WW + 1] * w11;
                }
                {
                    const float* p = img + (size_t)2 * HH * WW;
                    f2 += p[0] * w00 + p[1] * w01 + p[WW] * w10 + p[WW + 1] * w11;
                }
                cnt += 1.f;
            }
        }

        float2* op = (float2*)(out + (size_t)6 * n);

        if (cnt == 0.f) {
            op[0] = make_float2(0.f, 0.f);
            op[1] = make_float2(0.f, 0.f);
            op[2] = make_float2(0.f, 0.f);
            continue;
        }

        const float inv = 1.f / cnt;
        f0 *= inv; f1 *= inv; f2 *= inv;

        float a0 = sB2[0], a1 = sB2[1], a2 = sB2[2];
        #pragma unroll
        for (int j = 0; j < HID; ++j) {
            const float4 wa = sW14[j];
            const float4 wb = sW24[j];
            float h = fmaf(f0, wa.x, fmaf(f1, wa.y, fmaf(f2, wa.z, wa.w)));
            h = fmaxf(h, 0.f);
            a0 = fmaf(h, wb.x, a0);
            a1 = fmaf(h, wb.y, a1);
            a2 = fmaf(h, wb.z, a2);
        }

        op[0] = make_float2(tanhf(a0), tanhf(a1));
        op[1] = make_float2(tanhf(a2), __expf(lsc[3 * n + 0]));
        op[2] = make_float2(__expf(lsc[3 * n + 1]), __expf(lsc[3 * n + 2]));
    }
}

extern "C" void kernel_launch(void* const* d_in, const int* in_sizes, int n_in,
                              void* d_out, int out_size)
{
    const float* images = (const float*)d_in[0];
    const float* extr   = (const float*)d_in[1];
    const float* intr   = (const float*)d_in[2];
    const float* W1     = (const float*)d_in[3];
    const float* b1     = (const float*)d_in[4];
    const float* W2     = (const float*)d_in[5];
    const float* b2     = (const float*)d_in[6];
    const float* pcd    = (const float*)d_in[7];
    const float* lsc    = (const float*)d_in[8];
    const int*   dsp    = (const int*)  d_in[9];

    int N  = in_sizes[7] / 3;
    int NW = (N + 31) / 32;

    zero_ctr_kernel<<<1, 1>>>();

    // persistent-ish grid: enough blocks to fill the chip at expected occupancy
    int blocks = 148 * 4;
    sky_kernel<<<blocks, BT>>>(images, extr, intr, W1, b1, W2, b2,
                               pcd, lsc, dsp, (float*)d_out, N, NW);
}